// round 14
// baseline (speedup 1.0000x reference)
#include <cuda_runtime.h>
#include <cuda_bf16.h>
#include <math.h>
#include <stdint.h>

#define NN 50000
#define EE 1600000
#define GG 500
#define HH 128
#define NGG 50
#define LL 6

// ---------------- device scratch (static, no allocation) ----------------
__device__ int   g_cnt[NN];          // zero at start of every replay (scan3 self-cleans)
__device__ int   g_rowptr[NN + 1];
__device__ int   g_cursor[NN];
__device__ int   g_bsum[256];
__device__ __align__(16) uint2 g_ecd[EE];                           // packed (col, dist)
__device__ __align__(16) __nv_bfloat16 g_vb[(size_t)NN * HH];       // node features bf16
__device__ __align__(16) __nv_bfloat16 g_Pb[(size_t)NN * 256];      // [P0|P1] bf16
__device__ __align__(16) __nv_bfloat16 g_Mb[(size_t)LL * HH * 256]; // folded B^T [n][k] bf16

__device__ __forceinline__ float ssp_f(float x) {
  float sp = (x > 15.f) ? x : __logf(1.f + __expf(x));
  return sp - 0.6931471805599453f;
}

// ---------------- CSR build ----------------
__global__ void k_hist(const int* __restrict__ row) {
  int e = blockIdx.x * blockDim.x + threadIdx.x;
  if (e < EE) atomicAdd(&g_cnt[row[e]], 1);
}

__device__ __forceinline__ int block_incl_scan_256(int x, int* ws) {
  int lane = threadIdx.x & 31, w = threadIdx.x >> 5;
  int incl = x;
#pragma unroll
  for (int off = 1; off < 32; off <<= 1) {
    int y = __shfl_up_sync(0xffffffffu, incl, off);
    if (lane >= off) incl += y;
  }
  if (lane == 31) ws[w] = incl;
  __syncthreads();
  if (threadIdx.x == 0) {
    int s = 0;
#pragma unroll
    for (int j = 0; j < 8; j++) { int t = ws[j]; ws[j] = s; s += t; }
  }
  __syncthreads();
  return incl + ws[w];
}

__global__ void k_scan1() {
  __shared__ int ws[8];
  int i = blockIdx.x * 256 + threadIdx.x;
  int x = (i < NN) ? g_cnt[i] : 0;
  int incl = block_incl_scan_256(x, ws);
  if (i < NN) g_rowptr[i + 1] = incl;
  if (threadIdx.x == 255) g_bsum[blockIdx.x] = incl;
}

__global__ void k_scan2(int nblocks) {
  __shared__ int ws[8];
  int x = (threadIdx.x < nblocks) ? g_bsum[threadIdx.x] : 0;
  int incl = block_incl_scan_256(x, ws);
  if (threadIdx.x < nblocks) g_bsum[threadIdx.x] = incl - x;  // exclusive
}

__global__ void k_scan3() {
  int i = blockIdx.x * 256 + threadIdx.x;
  if (i < NN) {
    int fin = g_rowptr[i + 1] + g_bsum[blockIdx.x];
    g_rowptr[i + 1] = fin;
    g_cursor[i] = fin - g_cnt[i];
    g_cnt[i] = 0;  // self-clean for the next graph replay
    if (i == 0) g_rowptr[0] = 0;
  }
}

__global__ void k_scatter(const int* __restrict__ row, const int* __restrict__ col,
                          const float* __restrict__ pos) {
  int e = blockIdx.x * blockDim.x + threadIdx.x;
  if (e >= EE) return;
  int r = row[e], c = col[e];
  float dx = pos[3 * r + 0] - pos[3 * c + 0];
  float dy = pos[3 * r + 1] - pos[3 * c + 1];
  float dz = pos[3 * r + 2] - pos[3 * c + 2];
  float dist = sqrtf(dx * dx + dy * dy + dz * dz);
  int idx = atomicAdd(&g_cursor[r], 1);
  g_ecd[idx] = make_uint2((uint32_t)c, __float_as_uint(dist));
}

// ---------------- init node features + zero output ----------------
__global__ void k_init(const int* __restrict__ z, const float* __restrict__ emb,
                       float* __restrict__ out, int n_out) {
  int i = blockIdx.x * blockDim.x + threadIdx.x;
  if (i < n_out) out[i] = 0.f;
  if (i < NN * HH) {
    int n = i >> 7, f = i & 127;
    g_vb[i] = __float2bfloat16(emb[(z[n] << 7) + f]);
  }
}

// Mb[n][k] (bf16, B^T): M0 = (Wn .* c) @ Wo ; M1 = (Wn .* a) @ Wo
__global__ void k_prep(const float* __restrict__ dist_W, const float* __restrict__ dist_b,
                       const float* __restrict__ Wn, const float* __restrict__ We,
                       const float* __restrict__ be, const float* __restrict__ Wo) {
  int li = blockIdx.x;
  int tid = threadIdx.x;
  __shared__ float sa[128], sc[128];
  if (tid < 128) {
    float a = 0.f, c = 0.f;
    const float* we = We + (size_t)li * NGG * HH + tid;
#pragma unroll 10
    for (int g = 0; g < NGG; g++) {
      float w = we[(size_t)g * HH];
      a = fmaf(dist_W[g], w, a);
      c = fmaf(dist_b[g], w, c);
    }
    sa[tid] = a;
    sc[tid] = c + be[li * HH + tid];
  }
  __syncthreads();
  int k = blockIdx.y * 32 + (tid >> 3);  // K index 0..255
  int o0 = (tid & 7) << 4;               // 16 output cols
  int h = k & 127;
  const float* coef = (k >= 128) ? sa : sc;
  const float* wn = Wn + (size_t)li * HH * HH + (size_t)h * HH;
  const float* wo = Wo + (size_t)li * HH * HH + o0;
  float acc[16];
#pragma unroll
  for (int q = 0; q < 16; q++) acc[q] = 0.f;
  for (int f = 0; f < 128; f++) {
    float wf = wn[f] * coef[f];
    const float* wr = wo + (size_t)f * HH;
#pragma unroll
    for (int q = 0; q < 16; q++) acc[q] = fmaf(wf, wr[q], acc[q]);
  }
  __nv_bfloat16* dst = g_Mb + (size_t)li * HH * 256;
#pragma unroll
  for (int q = 0; q < 16; q++) dst[(size_t)(o0 + q) * 256 + k] = __float2bfloat16(acc[q]);
}

// ---------------- edge aggregation: P0 = sum v[col], P1 = sum dist*v[col] (bf16 io) ----------------
__global__ void k_edge() {
  int wg = (blockIdx.x * blockDim.x + threadIdx.x) >> 5;
  int lane = threadIdx.x & 31;
  if (wg >= NN) return;
  int s = g_rowptr[wg], e = g_rowptr[wg + 1];
  float a0 = 0.f, a1 = 0.f, a2 = 0.f, a3 = 0.f;
  float b0 = 0.f, b1 = 0.f, b2 = 0.f, b3 = 0.f;
  for (int base = s; base < e; base += 32) {
    int j = base + lane;
    int c = 0;
    float d = 0.f;
    if (j < e) {
      uint2 cd = g_ecd[j];
      c = (int)cd.x;
      d = __uint_as_float(cd.y);
    }
    int cnt = min(32, e - base);
#pragma unroll 4
    for (int t = 0; t < cnt; ++t) {
      int cc = __shfl_sync(0xffffffffu, c, t);
      float dd = __shfl_sync(0xffffffffu, d, t);
      uint2 raw = *(const uint2*)(g_vb + ((size_t)cc << 7) + (lane << 2));
      float2 f0 = __bfloat1622float2(*(__nv_bfloat162*)&raw.x);
      float2 f1 = __bfloat1622float2(*(__nv_bfloat162*)&raw.y);
      a0 += f0.x; a1 += f0.y; a2 += f1.x; a3 += f1.y;
      b0 = fmaf(dd, f0.x, b0);
      b1 = fmaf(dd, f0.y, b1);
      b2 = fmaf(dd, f1.x, b2);
      b3 = fmaf(dd, f1.y, b3);
    }
  }
  __nv_bfloat16* p = g_Pb + ((size_t)wg << 8);
  __nv_bfloat162 h0 = __float22bfloat162_rn(make_float2(a0, a1));
  __nv_bfloat162 h1 = __float22bfloat162_rn(make_float2(a2, a3));
  __nv_bfloat162 h2 = __float22bfloat162_rn(make_float2(b0, b1));
  __nv_bfloat162 h3 = __float22bfloat162_rn(make_float2(b2, b3));
  *(uint2*)(p + (lane << 2)) = make_uint2(*(uint32_t*)&h0, *(uint32_t*)&h1);
  *(uint2*)(p + 128 + (lane << 2)) = make_uint2(*(uint32_t*)&h2, *(uint32_t*)&h3);
}

// ---------------- mma.sync bf16 layer GEMM: v = ssp(P @ Mb^T + bo) ----------------
// CTA tile 128(M) x 128(N), K=256, 8 warps (4 along M x 2 along N).
#define LDAB 264
#define SMEM_GEMM (2 * 128 * LDAB * 2 + 512)

__device__ __forceinline__ void mma16816(float* d, const uint32_t* a, const uint32_t* b,
                                         const float* c) {
  asm volatile(
      "mma.sync.aligned.m16n8k16.row.col.f32.bf16.bf16.f32 "
      "{%0,%1,%2,%3}, {%4,%5,%6,%7}, {%8,%9}, {%10,%11,%12,%13};\n"
      : "=f"(d[0]), "=f"(d[1]), "=f"(d[2]), "=f"(d[3])
      : "r"(a[0]), "r"(a[1]), "r"(a[2]), "r"(a[3]), "r"(b[0]), "r"(b[1]),
        "f"(c[0]), "f"(c[1]), "f"(c[2]), "f"(c[3]));
}

__global__ __launch_bounds__(256) void k_gemm_mma(int layer, const float* __restrict__ bias) {
  extern __shared__ __nv_bfloat16 sm[];
  __nv_bfloat16* As = sm;                    // [128][LDAB]
  __nv_bfloat16* Bs = sm + 128 * LDAB;       // [128][LDAB]  (B^T: n rows, k cols)
  float* sbias = (float*)(Bs + 128 * LDAB);
  int tid = threadIdx.x;
  int row0 = blockIdx.x * 128;

  const __nv_bfloat16* Bsrc = g_Mb + (size_t)layer * HH * 256;
#pragma unroll
  for (int it = 0; it < 16; it++) {
    int lin = it * 256 + tid;        // 4096 uint4 per tile
    int r = lin >> 5;
    int c8 = (lin & 31) << 3;
    int gr = row0 + r;
    uint4 va = make_uint4(0, 0, 0, 0);
    if (gr < NN) va = *(const uint4*)(g_Pb + (size_t)gr * 256 + c8);
    *(uint4*)(As + r * LDAB + c8) = va;
    *(uint4*)(Bs + r * LDAB + c8) = *(const uint4*)(Bsrc + (size_t)r * 256 + c8);
  }
  if (tid < 128) sbias[tid] = bias[tid];
  __syncthreads();

  int warp = tid >> 5, lane = tid & 31;
  int mw = warp >> 1, nw = warp & 1;
  int mrow0 = mw * 32, ncol0 = nw * 64;
  int qr = lane >> 2, qc = lane & 3;

  float acc[2][8][4];
#pragma unroll
  for (int mi = 0; mi < 2; mi++)
#pragma unroll
    for (int ni = 0; ni < 8; ni++)
#pragma unroll
      for (int q = 0; q < 4; q++) acc[mi][ni][q] = 0.f;

#pragma unroll
  for (int kk = 0; kk < 16; kk++) {
    int kb = kk * 16 + qc * 2;
    uint32_t a[2][4], b[8][2];
#pragma unroll
    for (int mi = 0; mi < 2; mi++) {
      const __nv_bfloat16* ap = As + (mrow0 + mi * 16 + qr) * LDAB + kb;
      a[mi][0] = *(const uint32_t*)(ap);
      a[mi][1] = *(const uint32_t*)(ap + 8 * LDAB);
      a[mi][2] = *(const uint32_t*)(ap + 8);
      a[mi][3] = *(const uint32_t*)(ap + 8 * LDAB + 8);
    }
#pragma unroll
    for (int ni = 0; ni < 8; ni++) {
      const __nv_bfloat16* bp = Bs + (ncol0 + ni * 8 + qr) * LDAB + kb;
      b[ni][0] = *(const uint32_t*)(bp);
      b[ni][1] = *(const uint32_t*)(bp + 8);
    }
#pragma unroll
    for (int mi = 0; mi < 2; mi++)
#pragma unroll
      for (int ni = 0; ni < 8; ni++) mma16816(acc[mi][ni], a[mi], b[ni], acc[mi][ni]);
  }

  // epilogue: bias + ssp, write bf16
#pragma unroll
  for (int mi = 0; mi < 2; mi++) {
    int r1 = row0 + mrow0 + mi * 16 + qr;
    int r2 = r1 + 8;
#pragma unroll
    for (int ni = 0; ni < 8; ni++) {
      int cc = ncol0 + ni * 8 + qc * 2;
      float bz0 = sbias[cc], bz1 = sbias[cc + 1];
      if (r1 < NN) {
        __nv_bfloat162 o = __float22bfloat162_rn(
            make_float2(ssp_f(acc[mi][ni][0] + bz0), ssp_f(acc[mi][ni][1] + bz1)));
        *(uint32_t*)(g_vb + (size_t)r1 * 128 + cc) = *(uint32_t*)&o;
      }
      if (r2 < NN) {
        __nv_bfloat162 o = __float22bfloat162_rn(
            make_float2(ssp_f(acc[mi][ni][2] + bz0), ssp_f(acc[mi][ni][3] + bz1)));
        *(uint32_t*)(g_vb + (size_t)r2 * 128 + cc) = *(uint32_t*)&o;
      }
    }
  }
}

// ---------------- fused fp32 readout: out += ssp(v@W1+b1)@W2 + b2 (segment-summed) ----------------
__global__ __launch_bounds__(256) void k_ro(const float* __restrict__ W1,
                                            const float* __restrict__ b1,
                                            const float* __restrict__ W2,
                                            const float* __restrict__ b2,
                                            const int* __restrict__ batch,
                                            float* __restrict__ out) {
  __shared__ float As[16][64];
  __shared__ float Bs[16][64];
  __shared__ float sb1[64], sW2[64];
  int tid = threadIdx.x;
  int row0 = blockIdx.x * 64;
  int ty = tid >> 4, tx = tid & 15;
  float acc[4][4];
#pragma unroll
  for (int i = 0; i < 4; i++)
#pragma unroll
    for (int j = 0; j < 4; j++) acc[i][j] = 0.f;

  int a_r = tid >> 2, a_c = (tid & 3) << 2;
  int b_r = tid >> 4, b_c = (tid & 15) << 2;
  int grow = row0 + a_r;
  bool avalid = grow < NN;
  const __nv_bfloat16* Aptr = g_vb + (size_t)(avalid ? grow : 0) * 128 + a_c;
  if (tid < 64) { sb1[tid] = b1[tid]; sW2[tid] = W2[tid]; }

  for (int k0 = 0; k0 < 128; k0 += 16) {
    float2 f0 = make_float2(0.f, 0.f), f1 = make_float2(0.f, 0.f);
    if (avalid) {
      uint2 raw = *(const uint2*)(Aptr + k0);
      f0 = __bfloat1622float2(*(__nv_bfloat162*)&raw.x);
      f1 = __bfloat1622float2(*(__nv_bfloat162*)&raw.y);
    }
    float4 bv = *(const float4*)(W1 + (size_t)(k0 + b_r) * 64 + b_c);
    As[a_c + 0][a_r] = f0.x;
    As[a_c + 1][a_r] = f0.y;
    As[a_c + 2][a_r] = f1.x;
    As[a_c + 3][a_r] = f1.y;
    *(float4*)&Bs[b_r][b_c] = bv;
    __syncthreads();
#pragma unroll
    for (int kk = 0; kk < 16; kk++) {
      float a[4], b[4];
      *(float4*)(a) = *(const float4*)&As[kk][ty * 4];
      *(float4*)(b) = *(const float4*)&Bs[kk][tx * 4];
#pragma unroll
      for (int i = 0; i < 4; i++)
#pragma unroll
        for (int j = 0; j < 4; j++) acc[i][j] = fmaf(a[i], b[j], acc[i][j]);
    }
    __syncthreads();
  }

  float bz2 = b2[0];
#pragma unroll
  for (int i = 0; i < 4; i++) {
    int r = row0 + ty * 4 + i;
    float p = 0.f;
#pragma unroll
    for (int j = 0; j < 4; j++)
      p = fmaf(ssp_f(acc[i][j] + sb1[tx * 4 + j]), sW2[tx * 4 + j], p);
    p += __shfl_xor_sync(0xffffffffu, p, 1);
    p += __shfl_xor_sync(0xffffffffu, p, 2);
    p += __shfl_xor_sync(0xffffffffu, p, 4);
    p += __shfl_xor_sync(0xffffffffu, p, 8);
    if (tx == 0 && r < NN) atomicAdd(&out[batch[r]], p + bz2);
  }
}

// ---------------- launch ----------------
extern "C" void kernel_launch(void* const* d_in, const int* in_sizes, int n_in,
                              void* d_out, int out_size) {
  (void)in_sizes; (void)n_in;
  const int* z = (const int*)d_in[0];
  const float* pos = (const float*)d_in[1];
  const int* batch = (const int*)d_in[2];
  const int* ei = (const int*)d_in[3];
  const float* emb = (const float*)d_in[4];
  const float* dist_W = (const float*)d_in[5];
  const float* dist_b = (const float*)d_in[6];
  const float* Wn = (const float*)d_in[7];
  const float* We = (const float*)d_in[8];
  const float* be = (const float*)d_in[9];
  const float* Wo = (const float*)d_in[10];
  const float* bo = (const float*)d_in[11];
  const float* W1 = (const float*)d_in[12];
  const float* b1 = (const float*)d_in[13];
  const float* W2 = (const float*)d_in[14];
  const float* b2 = (const float*)d_in[15];
  float* out = (float*)d_out;

  const int* row = ei;
  const int* col = ei + EE;

  static bool attr_set = false;
  if (!attr_set) {
    cudaFuncSetAttribute(k_gemm_mma, cudaFuncAttributeMaxDynamicSharedMemorySize, SMEM_GEMM);
    attr_set = true;
  }

  const int nscan = (NN + 255) / 256;  // 196

  // CSR build (counting sort by destination row; g_cnt is zero from static init
  // on the first call and self-cleaned by k_scan3 on every subsequent replay)
  k_hist<<<(EE + 255) / 256, 256>>>(row);
  k_scan1<<<nscan, 256>>>();
  k_scan2<<<1, 256>>>(nscan);
  k_scan3<<<nscan, 256>>>();
  k_scatter<<<(EE + 255) / 256, 256>>>(row, col, pos);

  // init node features + zero output, fold per-layer weights
  k_init<<<(NN * HH + 255) / 256, 256>>>(z, emb, out, out_size);
  k_prep<<<dim3(LL, 8), 256>>>(dist_W, dist_b, Wn, We, be, Wo);

  // 6 message-passing layers
  const int ngemm = (NN + 127) / 128;  // 391
  for (int i = 0; i < LL; i++) {
    k_edge<<<(NN * 32 + 255) / 256, 256>>>();
    k_gemm_mma<<<ngemm, 256, SMEM_GEMM>>>(i, bo + i * HH);
  }

  // fused fp32 readout
  k_ro<<<(NN + 63) / 64, 256>>>(W1, b1, W2, b2, batch, out);
}

// round 15
// speedup vs baseline: 1.4105x; 1.4105x over previous
#include <cuda_runtime.h>
#include <cuda_bf16.h>
#include <math.h>
#include <stdint.h>

#define NN 50000
#define EE 1600000
#define GG 500
#define HH 128
#define NGG 50
#define LL 6

// ---------------- device scratch (static, no allocation) ----------------
__device__ int   g_cnt[NN];          // zero at start of every replay (scan3 self-cleans)
__device__ int   g_rowptr[NN + 1];
__device__ int   g_cursor[NN];
__device__ int   g_bsum[256];
__device__ __align__(16) uint2 g_ecd[EE];                           // packed (col, dist)
__device__ __align__(16) __nv_bfloat16 g_vb[(size_t)NN * HH];       // node features bf16
__device__ __align__(16) __nv_bfloat16 g_Pb[(size_t)NN * 256];      // [P0|P1] bf16
__device__ __align__(16) __nv_bfloat16 g_Mb[(size_t)LL * HH * 256]; // folded B^T [n][k] bf16

__device__ __forceinline__ float ssp_f(float x) {
  float sp = (x > 15.f) ? x : __logf(1.f + __expf(x));
  return sp - 0.6931471805599453f;
}

// ---------------- CSR build ----------------
__global__ void k_hist(const int* __restrict__ row) {
  int e = blockIdx.x * blockDim.x + threadIdx.x;
  if (e < EE) atomicAdd(&g_cnt[row[e]], 1);
}

__device__ __forceinline__ int block_incl_scan_256(int x, int* ws) {
  int lane = threadIdx.x & 31, w = threadIdx.x >> 5;
  int incl = x;
#pragma unroll
  for (int off = 1; off < 32; off <<= 1) {
    int y = __shfl_up_sync(0xffffffffu, incl, off);
    if (lane >= off) incl += y;
  }
  if (lane == 31) ws[w] = incl;
  __syncthreads();
  if (threadIdx.x == 0) {
    int s = 0;
#pragma unroll
    for (int j = 0; j < 8; j++) { int t = ws[j]; ws[j] = s; s += t; }
  }
  __syncthreads();
  return incl + ws[w];
}

__global__ void k_scan1() {
  __shared__ int ws[8];
  int i = blockIdx.x * 256 + threadIdx.x;
  int x = (i < NN) ? g_cnt[i] : 0;
  int incl = block_incl_scan_256(x, ws);
  if (i < NN) g_rowptr[i + 1] = incl;
  if (threadIdx.x == 255) g_bsum[blockIdx.x] = incl;
}

__global__ void k_scan2(int nblocks) {
  __shared__ int ws[8];
  int x = (threadIdx.x < nblocks) ? g_bsum[threadIdx.x] : 0;
  int incl = block_incl_scan_256(x, ws);
  if (threadIdx.x < nblocks) g_bsum[threadIdx.x] = incl - x;  // exclusive
}

__global__ void k_scan3() {
  int i = blockIdx.x * 256 + threadIdx.x;
  if (i < NN) {
    int fin = g_rowptr[i + 1] + g_bsum[blockIdx.x];
    g_rowptr[i + 1] = fin;
    g_cursor[i] = fin - g_cnt[i];
    g_cnt[i] = 0;  // self-clean for the next graph replay
    if (i == 0) g_rowptr[0] = 0;
  }
}

__global__ void k_scatter(const int* __restrict__ row, const int* __restrict__ col,
                          const float* __restrict__ pos) {
  int e = blockIdx.x * blockDim.x + threadIdx.x;
  if (e >= EE) return;
  int r = row[e], c = col[e];
  float dx = pos[3 * r + 0] - pos[3 * c + 0];
  float dy = pos[3 * r + 1] - pos[3 * c + 1];
  float dz = pos[3 * r + 2] - pos[3 * c + 2];
  float dist = sqrtf(dx * dx + dy * dy + dz * dz);
  int idx = atomicAdd(&g_cursor[r], 1);
  g_ecd[idx] = make_uint2((uint32_t)c, __float_as_uint(dist));
}

// ---------------- init node features + zero output ----------------
__global__ void k_init(const int* __restrict__ z, const float* __restrict__ emb,
                       float* __restrict__ out, int n_out) {
  int i = blockIdx.x * blockDim.x + threadIdx.x;
  if (i < n_out) out[i] = 0.f;
  if (i < NN * HH) {
    int n = i >> 7, f = i & 127;
    g_vb[i] = __float2bfloat16(emb[(z[n] << 7) + f]);
  }
}

// Mb[n][k] (bf16, B^T): M0 = (Wn .* c) @ Wo ; M1 = (Wn .* a) @ Wo
__global__ void k_prep(const float* __restrict__ dist_W, const float* __restrict__ dist_b,
                       const float* __restrict__ Wn, const float* __restrict__ We,
                       const float* __restrict__ be, const float* __restrict__ Wo) {
  int li = blockIdx.x;
  int tid = threadIdx.x;
  __shared__ float sa[128], sc[128];
  if (tid < 128) {
    float a = 0.f, c = 0.f;
    const float* we = We + (size_t)li * NGG * HH + tid;
#pragma unroll 10
    for (int g = 0; g < NGG; g++) {
      float w = we[(size_t)g * HH];
      a = fmaf(dist_W[g], w, a);
      c = fmaf(dist_b[g], w, c);
    }
    sa[tid] = a;
    sc[tid] = c + be[li * HH + tid];
  }
  __syncthreads();
  int k = blockIdx.y * 32 + (tid >> 3);  // K index 0..255
  int o0 = (tid & 7) << 4;               // 16 output cols
  int h = k & 127;
  const float* coef = (k >= 128) ? sa : sc;
  const float* wn = Wn + (size_t)li * HH * HH + (size_t)h * HH;
  const float* wo = Wo + (size_t)li * HH * HH + o0;
  float acc[16];
#pragma unroll
  for (int q = 0; q < 16; q++) acc[q] = 0.f;
  for (int f = 0; f < 128; f++) {
    float wf = wn[f] * coef[f];
    const float* wr = wo + (size_t)f * HH;
#pragma unroll
    for (int q = 0; q < 16; q++) acc[q] = fmaf(wf, wr[q], acc[q]);
  }
  __nv_bfloat16* dst = g_Mb + (size_t)li * HH * 256;
#pragma unroll
  for (int q = 0; q < 16; q++) dst[(size_t)(o0 + q) * 256 + k] = __float2bfloat16(acc[q]);
}

// ---------------- edge aggregation (2-edge vectorized) ----------------
// Warp per row. Half-warp 0 handles even edges, half-warp 1 odd edges; each
// lane owns 8 features (uint4 = 8 bf16 per gather). Final xor-16 combine.
__global__ void k_edge() {
  int wg = (blockIdx.x * blockDim.x + threadIdx.x) >> 5;
  int lane = threadIdx.x & 31;
  if (wg >= NN) return;
  int s = g_rowptr[wg], e = g_rowptr[wg + 1];
  int half = lane >> 4;          // 0: even edges, 1: odd edges
  int fl = (lane & 15) << 3;     // feature base (8 features per lane)
  float a[8], b[8];
#pragma unroll
  for (int i = 0; i < 8; i++) { a[i] = 0.f; b[i] = 0.f; }

  for (int base = s; base < e; base += 32) {
    int j = base + lane;
    int c = 0;
    float d = 0.f;
    if (j < e) {
      uint2 cd = g_ecd[j];
      c = (int)cd.x;
      d = __uint_as_float(cd.y);
    }
    int cnt = min(32, e - base);
#pragma unroll 4
    for (int t = 0; t < cnt; t += 2) {
      int src = t + half;
      int cc = __shfl_sync(0xffffffffu, c, src);
      float dd = __shfl_sync(0xffffffffu, d, src);
      uint4 raw = make_uint4(0, 0, 0, 0);
      if (src < cnt) raw = *(const uint4*)(g_vb + ((size_t)cc << 7) + fl);
      float2 f0 = __bfloat1622float2(*(__nv_bfloat162*)&raw.x);
      float2 f1 = __bfloat1622float2(*(__nv_bfloat162*)&raw.y);
      float2 f2 = __bfloat1622float2(*(__nv_bfloat162*)&raw.z);
      float2 f3 = __bfloat1622float2(*(__nv_bfloat162*)&raw.w);
      a[0] += f0.x; a[1] += f0.y; a[2] += f1.x; a[3] += f1.y;
      a[4] += f2.x; a[5] += f2.y; a[6] += f3.x; a[7] += f3.y;
      b[0] = fmaf(dd, f0.x, b[0]); b[1] = fmaf(dd, f0.y, b[1]);
      b[2] = fmaf(dd, f1.x, b[2]); b[3] = fmaf(dd, f1.y, b[3]);
      b[4] = fmaf(dd, f2.x, b[4]); b[5] = fmaf(dd, f2.y, b[5]);
      b[6] = fmaf(dd, f3.x, b[6]); b[7] = fmaf(dd, f3.y, b[7]);
    }
  }
  // combine even/odd halves (lanes l and l^16 hold partial sums of same features)
#pragma unroll
  for (int i = 0; i < 8; i++) {
    a[i] += __shfl_xor_sync(0xffffffffu, a[i], 16);
    b[i] += __shfl_xor_sync(0xffffffffu, b[i], 16);
  }
  // write: lanes 0-15 write P0[fl..fl+8), lanes 16-31 write P1[fl..fl+8)
  const float* srcv = (half == 0) ? a : b;
  __nv_bfloat162 h0 = __float22bfloat162_rn(make_float2(srcv[0], srcv[1]));
  __nv_bfloat162 h1 = __float22bfloat162_rn(make_float2(srcv[2], srcv[3]));
  __nv_bfloat162 h2 = __float22bfloat162_rn(make_float2(srcv[4], srcv[5]));
  __nv_bfloat162 h3 = __float22bfloat162_rn(make_float2(srcv[6], srcv[7]));
  __nv_bfloat16* p = g_Pb + ((size_t)wg << 8) + half * 128 + fl;
  *(uint4*)p = make_uint4(*(uint32_t*)&h0, *(uint32_t*)&h1,
                          *(uint32_t*)&h2, *(uint32_t*)&h3);
}

// ---------------- mma.sync bf16 layer GEMM: v = ssp(P @ Mb^T + bo) ----------------
// CTA tile 128(M) x 128(N), K=256, 8 warps (4 along M x 2 along N).
#define LDAB 264
#define SMEM_GEMM (2 * 128 * LDAB * 2 + 512)

__device__ __forceinline__ void mma16816(float* d, const uint32_t* a, const uint32_t* b,
                                         const float* c) {
  asm volatile(
      "mma.sync.aligned.m16n8k16.row.col.f32.bf16.bf16.f32 "
      "{%0,%1,%2,%3}, {%4,%5,%6,%7}, {%8,%9}, {%10,%11,%12,%13};\n"
      : "=f"(d[0]), "=f"(d[1]), "=f"(d[2]), "=f"(d[3])
      : "r"(a[0]), "r"(a[1]), "r"(a[2]), "r"(a[3]), "r"(b[0]), "r"(b[1]),
        "f"(c[0]), "f"(c[1]), "f"(c[2]), "f"(c[3]));
}

__global__ __launch_bounds__(256) void k_gemm_mma(int layer, const float* __restrict__ bias) {
  extern __shared__ __nv_bfloat16 sm[];
  __nv_bfloat16* As = sm;                    // [128][LDAB]
  __nv_bfloat16* Bs = sm + 128 * LDAB;       // [128][LDAB]  (B^T: n rows, k cols)
  float* sbias = (float*)(Bs + 128 * LDAB);
  int tid = threadIdx.x;
  int row0 = blockIdx.x * 128;

  const __nv_bfloat16* Bsrc = g_Mb + (size_t)layer * HH * 256;
#pragma unroll
  for (int it = 0; it < 16; it++) {
    int lin = it * 256 + tid;        // 4096 uint4 per tile
    int r = lin >> 5;
    int c8 = (lin & 31) << 3;
    int gr = row0 + r;
    uint4 va = make_uint4(0, 0, 0, 0);
    if (gr < NN) va = *(const uint4*)(g_Pb + (size_t)gr * 256 + c8);
    *(uint4*)(As + r * LDAB + c8) = va;
    *(uint4*)(Bs + r * LDAB + c8) = *(const uint4*)(Bsrc + (size_t)r * 256 + c8);
  }
  if (tid < 128) sbias[tid] = bias[tid];
  __syncthreads();

  int warp = tid >> 5, lane = tid & 31;
  int mw = warp >> 1, nw = warp & 1;
  int mrow0 = mw * 32, ncol0 = nw * 64;
  int qr = lane >> 2, qc = lane & 3;

  float acc[2][8][4];
#pragma unroll
  for (int mi = 0; mi < 2; mi++)
#pragma unroll
    for (int ni = 0; ni < 8; ni++)
#pragma unroll
      for (int q = 0; q < 4; q++) acc[mi][ni][q] = 0.f;

#pragma unroll
  for (int kk = 0; kk < 16; kk++) {
    int kb = kk * 16 + qc * 2;
    uint32_t a[2][4], b[8][2];
#pragma unroll
    for (int mi = 0; mi < 2; mi++) {
      const __nv_bfloat16* ap = As + (mrow0 + mi * 16 + qr) * LDAB + kb;
      a[mi][0] = *(const uint32_t*)(ap);
      a[mi][1] = *(const uint32_t*)(ap + 8 * LDAB);
      a[mi][2] = *(const uint32_t*)(ap + 8);
      a[mi][3] = *(const uint32_t*)(ap + 8 * LDAB + 8);
    }
#pragma unroll
    for (int ni = 0; ni < 8; ni++) {
      const __nv_bfloat16* bp = Bs + (ncol0 + ni * 8 + qr) * LDAB + kb;
      b[ni][0] = *(const uint32_t*)(bp);
      b[ni][1] = *(const uint32_t*)(bp + 8);
    }
#pragma unroll
    for (int mi = 0; mi < 2; mi++)
#pragma unroll
      for (int ni = 0; ni < 8; ni++) mma16816(acc[mi][ni], a[mi], b[ni], acc[mi][ni]);
  }

  // epilogue: bias + ssp, write bf16
#pragma unroll
  for (int mi = 0; mi < 2; mi++) {
    int r1 = row0 + mrow0 + mi * 16 + qr;
    int r2 = r1 + 8;
#pragma unroll
    for (int ni = 0; ni < 8; ni++) {
      int cc = ncol0 + ni * 8 + qc * 2;
      float bz0 = sbias[cc], bz1 = sbias[cc + 1];
      if (r1 < NN) {
        __nv_bfloat162 o = __float22bfloat162_rn(
            make_float2(ssp_f(acc[mi][ni][0] + bz0), ssp_f(acc[mi][ni][1] + bz1)));
        *(uint32_t*)(g_vb + (size_t)r1 * 128 + cc) = *(uint32_t*)&o;
      }
      if (r2 < NN) {
        __nv_bfloat162 o = __float22bfloat162_rn(
            make_float2(ssp_f(acc[mi][ni][2] + bz0), ssp_f(acc[mi][ni][3] + bz1)));
        *(uint32_t*)(g_vb + (size_t)r2 * 128 + cc) = *(uint32_t*)&o;
      }
    }
  }
}

// ---------------- fused fp32 readout: out += ssp(v@W1+b1)@W2 + b2 (segment-summed) ----------------
__global__ __launch_bounds__(256) void k_ro(const float* __restrict__ W1,
                                            const float* __restrict__ b1,
                                            const float* __restrict__ W2,
                                            const float* __restrict__ b2,
                                            const int* __restrict__ batch,
                                            float* __restrict__ out) {
  __shared__ float As[16][64];
  __shared__ float Bs[16][64];
  __shared__ float sb1[64], sW2[64];
  int tid = threadIdx.x;
  int row0 = blockIdx.x * 64;
  int ty = tid >> 4, tx = tid & 15;
  float acc[4][4];
#pragma unroll
  for (int i = 0; i < 4; i++)
#pragma unroll
    for (int j = 0; j < 4; j++) acc[i][j] = 0.f;

  int a_r = tid >> 2, a_c = (tid & 3) << 2;
  int b_r = tid >> 4, b_c = (tid & 15) << 2;
  int grow = row0 + a_r;
  bool avalid = grow < NN;
  const __nv_bfloat16* Aptr = g_vb + (size_t)(avalid ? grow : 0) * 128 + a_c;
  if (tid < 64) { sb1[tid] = b1[tid]; sW2[tid] = W2[tid]; }

  for (int k0 = 0; k0 < 128; k0 += 16) {
    float2 f0 = make_float2(0.f, 0.f), f1 = make_float2(0.f, 0.f);
    if (avalid) {
      uint2 raw = *(const uint2*)(Aptr + k0);
      f0 = __bfloat1622float2(*(__nv_bfloat162*)&raw.x);
      f1 = __bfloat1622float2(*(__nv_bfloat162*)&raw.y);
    }
    float4 bv = *(const float4*)(W1 + (size_t)(k0 + b_r) * 64 + b_c);
    As[a_c + 0][a_r] = f0.x;
    As[a_c + 1][a_r] = f0.y;
    As[a_c + 2][a_r] = f1.x;
    As[a_c + 3][a_r] = f1.y;
    *(float4*)&Bs[b_r][b_c] = bv;
    __syncthreads();
#pragma unroll
    for (int kk = 0; kk < 16; kk++) {
      float a[4], b[4];
      *(float4*)(a) = *(const float4*)&As[kk][ty * 4];
      *(float4*)(b) = *(const float4*)&Bs[kk][tx * 4];
#pragma unroll
      for (int i = 0; i < 4; i++)
#pragma unroll
        for (int j = 0; j < 4; j++) acc[i][j] = fmaf(a[i], b[j], acc[i][j]);
    }
    __syncthreads();
  }

  float bz2 = b2[0];
#pragma unroll
  for (int i = 0; i < 4; i++) {
    int r = row0 + ty * 4 + i;
    float p = 0.f;
#pragma unroll
    for (int j = 0; j < 4; j++)
      p = fmaf(ssp_f(acc[i][j] + sb1[tx * 4 + j]), sW2[tx * 4 + j], p);
    p += __shfl_xor_sync(0xffffffffu, p, 1);
    p += __shfl_xor_sync(0xffffffffu, p, 2);
    p += __shfl_xor_sync(0xffffffffu, p, 4);
    p += __shfl_xor_sync(0xffffffffu, p, 8);
    if (tx == 0 && r < NN) atomicAdd(&out[batch[r]], p + bz2);
  }
}

// ---------------- launch ----------------
extern "C" void kernel_launch(void* const* d_in, const int* in_sizes, int n_in,
                              void* d_out, int out_size) {
  (void)in_sizes; (void)n_in;
  const int* z = (const int*)d_in[0];
  const float* pos = (const float*)d_in[1];
  const int* batch = (const int*)d_in[2];
  const int* ei = (const int*)d_in[3];
  const float* emb = (const float*)d_in[4];
  const float* dist_W = (const float*)d_in[5];
  const float* dist_b = (const float*)d_in[6];
  const float* Wn = (const float*)d_in[7];
  const float* We = (const float*)d_in[8];
  const float* be = (const float*)d_in[9];
  const float* Wo = (const float*)d_in[10];
  const float* bo = (const float*)d_in[11];
  const float* W1 = (const float*)d_in[12];
  const float* b1 = (const float*)d_in[13];
  const float* W2 = (const float*)d_in[14];
  const float* b2 = (const float*)d_in[15];
  float* out = (float*)d_out;

  const int* row = ei;
  const int* col = ei + EE;

  static bool attr_set = false;
  if (!attr_set) {
    cudaFuncSetAttribute(k_gemm_mma, cudaFuncAttributeMaxDynamicSharedMemorySize, SMEM_GEMM);
    attr_set = true;
  }

  const int nscan = (NN + 255) / 256;  // 196

  // CSR build (counting sort by destination row; g_cnt is zero from static init
  // on the first call and self-cleaned by k_scan3 on every subsequent replay)
  k_hist<<<(EE + 255) / 256, 256>>>(row);
  k_scan1<<<nscan, 256>>>();
  k_scan2<<<1, 256>>>(nscan);
  k_scan3<<<nscan, 256>>>();
  k_scatter<<<(EE + 255) / 256, 256>>>(row, col, pos);

  // init node features + zero output, fold per-layer weights
  k_init<<<(NN * HH + 255) / 256, 256>>>(z, emb, out, out_size);
  k_prep<<<dim3(LL, 8), 256>>>(dist_W, dist_b, Wn, We, be, Wo);

  // 6 message-passing layers
  const int ngemm = (NN + 127) / 128;  // 391
  for (int i = 0; i < LL; i++) {
    k_edge<<<(NN * 32 + 255) / 256, 256>>>();
    k_gemm_mma<<<ngemm, 256, SMEM_GEMM>>>(i, bo + i * HH);
  }

  // fused fp32 readout
  k_ro<<<(NN + 63) / 64, 256>>>(W1, b1, W2, b2, batch, out);
}

// round 16
// speedup vs baseline: 1.5920x; 1.1287x over previous
#include <cuda_runtime.h>
#include <cuda_bf16.h>
#include <math.h>
#include <stdint.h>

#define NN 50000
#define EE 1600000
#define GG 500
#define HH 128
#define NGG 50
#define LL 6

// ---------------- device scratch (static, no allocation) ----------------
__device__ int   g_cnt[NN];          // zero at start of every replay (scan3 self-cleans)
__device__ int   g_rowptr[NN + 1];
__device__ int   g_cursor[NN];
__device__ int   g_bsum[256];
__device__ __align__(16) uint2 g_ecd[EE];                           // packed (col, dist)
__device__ __align__(16) __nv_bfloat16 g_vb[(size_t)NN * HH];       // node features bf16
__device__ __align__(16) __nv_bfloat16 g_Pb[(size_t)NN * 256];      // [P0|P1] bf16
__device__ __align__(16) __nv_bfloat16 g_Mb[(size_t)LL * HH * 256]; // folded B^T [n][k] bf16

__device__ __forceinline__ float ssp_f(float x) {
  float sp = (x > 15.f) ? x : __logf(1.f + __expf(x));
  return sp - 0.6931471805599453f;
}

// ---------------- CSR build ----------------
__global__ void k_hist(const int* __restrict__ row) {
  int e = blockIdx.x * blockDim.x + threadIdx.x;
  if (e < EE) atomicAdd(&g_cnt[row[e]], 1);
}

__device__ __forceinline__ int block_incl_scan_256(int x, int* ws) {
  int lane = threadIdx.x & 31, w = threadIdx.x >> 5;
  int incl = x;
#pragma unroll
  for (int off = 1; off < 32; off <<= 1) {
    int y = __shfl_up_sync(0xffffffffu, incl, off);
    if (lane >= off) incl += y;
  }
  if (lane == 31) ws[w] = incl;
  __syncthreads();
  if (threadIdx.x == 0) {
    int s = 0;
#pragma unroll
    for (int j = 0; j < 8; j++) { int t = ws[j]; ws[j] = s; s += t; }
  }
  __syncthreads();
  return incl + ws[w];
}

__global__ void k_scan1() {
  __shared__ int ws[8];
  int i = blockIdx.x * 256 + threadIdx.x;
  int x = (i < NN) ? g_cnt[i] : 0;
  int incl = block_incl_scan_256(x, ws);
  if (i < NN) g_rowptr[i + 1] = incl;
  if (threadIdx.x == 255) g_bsum[blockIdx.x] = incl;
}

__global__ void k_scan2(int nblocks) {
  __shared__ int ws[8];
  int x = (threadIdx.x < nblocks) ? g_bsum[threadIdx.x] : 0;
  int incl = block_incl_scan_256(x, ws);
  if (threadIdx.x < nblocks) g_bsum[threadIdx.x] = incl - x;  // exclusive
}

__global__ void k_scan3() {
  int i = blockIdx.x * 256 + threadIdx.x;
  if (i < NN) {
    int fin = g_rowptr[i + 1] + g_bsum[blockIdx.x];
    g_rowptr[i + 1] = fin;
    g_cursor[i] = fin - g_cnt[i];
    g_cnt[i] = 0;  // self-clean for the next graph replay
    if (i == 0) g_rowptr[0] = 0;
  }
}

__global__ void k_scatter(const int* __restrict__ row, const int* __restrict__ col,
                          const float* __restrict__ pos) {
  int e = blockIdx.x * blockDim.x + threadIdx.x;
  if (e >= EE) return;
  int r = row[e], c = col[e];
  float dx = pos[3 * r + 0] - pos[3 * c + 0];
  float dy = pos[3 * r + 1] - pos[3 * c + 1];
  float dz = pos[3 * r + 2] - pos[3 * c + 2];
  float dist = sqrtf(dx * dx + dy * dy + dz * dz);
  int idx = atomicAdd(&g_cursor[r], 1);
  g_ecd[idx] = make_uint2((uint32_t)c, __float_as_uint(dist));
}

// ---------------- init node features + zero output ----------------
__global__ void k_init(const int* __restrict__ z, const float* __restrict__ emb,
                       float* __restrict__ out, int n_out) {
  int i = blockIdx.x * blockDim.x + threadIdx.x;
  if (i < n_out) out[i] = 0.f;
  if (i < NN * HH) {
    int n = i >> 7, f = i & 127;
    g_vb[i] = __float2bfloat16(emb[(z[n] << 7) + f]);
  }
}

// Mb[n][k] (bf16, B^T): M0 = (Wn .* c) @ Wo ; M1 = (Wn .* a) @ Wo
__global__ void k_prep(const float* __restrict__ dist_W, const float* __restrict__ dist_b,
                       const float* __restrict__ Wn, const float* __restrict__ We,
                       const float* __restrict__ be, const float* __restrict__ Wo) {
  int li = blockIdx.x;
  int tid = threadIdx.x;
  __shared__ float sa[128], sc[128];
  if (tid < 128) {
    float a = 0.f, c = 0.f;
    const float* we = We + (size_t)li * NGG * HH + tid;
#pragma unroll 10
    for (int g = 0; g < NGG; g++) {
      float w = we[(size_t)g * HH];
      a = fmaf(dist_W[g], w, a);
      c = fmaf(dist_b[g], w, c);
    }
    sa[tid] = a;
    sc[tid] = c + be[li * HH + tid];
  }
  __syncthreads();
  int k = blockIdx.y * 32 + (tid >> 3);  // K index 0..255
  int o0 = (tid & 7) << 4;               // 16 output cols
  int h = k & 127;
  const float* coef = (k >= 128) ? sa : sc;
  const float* wn = Wn + (size_t)li * HH * HH + (size_t)h * HH;
  const float* wo = Wo + (size_t)li * HH * HH + o0;
  float acc[16];
#pragma unroll
  for (int q = 0; q < 16; q++) acc[q] = 0.f;
  for (int f = 0; f < 128; f++) {
    float wf = wn[f] * coef[f];
    const float* wr = wo + (size_t)f * HH;
#pragma unroll
    for (int q = 0; q < 16; q++) acc[q] = fmaf(wf, wr[q], acc[q]);
  }
  __nv_bfloat16* dst = g_Mb + (size_t)li * HH * 256;
#pragma unroll
  for (int q = 0; q < 16; q++) dst[(size_t)(o0 + q) * 256 + k] = __float2bfloat16(acc[q]);
}

// ---------------- edge aggregation: P0 = sum v[col], P1 = sum dist*v[col] (bf16 io) ----------------
__global__ void k_edge() {
  int wg = (blockIdx.x * blockDim.x + threadIdx.x) >> 5;
  int lane = threadIdx.x & 31;
  if (wg >= NN) return;
  int s = g_rowptr[wg], e = g_rowptr[wg + 1];
  float a0 = 0.f, a1 = 0.f, a2 = 0.f, a3 = 0.f;
  float b0 = 0.f, b1 = 0.f, b2 = 0.f, b3 = 0.f;
  for (int base = s; base < e; base += 32) {
    int j = base + lane;
    int c = 0;
    float d = 0.f;
    if (j < e) {
      uint2 cd = g_ecd[j];
      c = (int)cd.x;
      d = __uint_as_float(cd.y);
    }
    int cnt = min(32, e - base);
#pragma unroll 4
    for (int t = 0; t < cnt; ++t) {
      int cc = __shfl_sync(0xffffffffu, c, t);
      float dd = __shfl_sync(0xffffffffu, d, t);
      uint2 raw = *(const uint2*)(g_vb + ((size_t)cc << 7) + (lane << 2));
      float2 f0 = __bfloat1622float2(*(__nv_bfloat162*)&raw.x);
      float2 f1 = __bfloat1622float2(*(__nv_bfloat162*)&raw.y);
      a0 += f0.x; a1 += f0.y; a2 += f1.x; a3 += f1.y;
      b0 = fmaf(dd, f0.x, b0);
      b1 = fmaf(dd, f0.y, b1);
      b2 = fmaf(dd, f1.x, b2);
      b3 = fmaf(dd, f1.y, b3);
    }
  }
  __nv_bfloat16* p = g_Pb + ((size_t)wg << 8);
  __nv_bfloat162 h0 = __float22bfloat162_rn(make_float2(a0, a1));
  __nv_bfloat162 h1 = __float22bfloat162_rn(make_float2(a2, a3));
  __nv_bfloat162 h2 = __float22bfloat162_rn(make_float2(b0, b1));
  __nv_bfloat162 h3 = __float22bfloat162_rn(make_float2(b2, b3));
  *(uint2*)(p + (lane << 2)) = make_uint2(*(uint32_t*)&h0, *(uint32_t*)&h1);
  *(uint2*)(p + 128 + (lane << 2)) = make_uint2(*(uint32_t*)&h2, *(uint32_t*)&h3);
}

// ---------------- mma.sync bf16 layer GEMM: v = ssp(P @ Mb^T + bo) ----------------
// N-split tiles: CTA tile 128(M) x 64(N), K=256, 8 warps (4 along M x 2 along N).
// SMEM ~102 KB -> 2 CTAs/SM: one CTA's tile load overlaps the other's mma.
#define LDAB 264
#define SMEM_GEMM ((128 + 64) * LDAB * 2 + 512)

__device__ __forceinline__ void mma16816(float* d, const uint32_t* a, const uint32_t* b,
                                         const float* c) {
  asm volatile(
      "mma.sync.aligned.m16n8k16.row.col.f32.bf16.bf16.f32 "
      "{%0,%1,%2,%3}, {%4,%5,%6,%7}, {%8,%9}, {%10,%11,%12,%13};\n"
      : "=f"(d[0]), "=f"(d[1]), "=f"(d[2]), "=f"(d[3])
      : "r"(a[0]), "r"(a[1]), "r"(a[2]), "r"(a[3]), "r"(b[0]), "r"(b[1]),
        "f"(c[0]), "f"(c[1]), "f"(c[2]), "f"(c[3]));
}

__global__ __launch_bounds__(256) void k_gemm_mma(int layer, const float* __restrict__ bias) {
  extern __shared__ __nv_bfloat16 sm[];
  __nv_bfloat16* As = sm;                    // [128][LDAB]
  __nv_bfloat16* Bs = sm + 128 * LDAB;       // [64][LDAB]  (B^T slice: n rows, k cols)
  float* sbias = (float*)(Bs + 64 * LDAB);   // 64 local bias entries
  int tid = threadIdx.x;
  int row0 = blockIdx.x * 128;
  int ncol_base = blockIdx.y * 64;

  const __nv_bfloat16* Bsrc = g_Mb + (size_t)layer * HH * 256 + (size_t)ncol_base * 256;
  // A tile: 4096 uint4
#pragma unroll
  for (int it = 0; it < 16; it++) {
    int lin = it * 256 + tid;
    int r = lin >> 5;
    int c8 = (lin & 31) << 3;
    int gr = row0 + r;
    uint4 va = make_uint4(0, 0, 0, 0);
    if (gr < NN) va = *(const uint4*)(g_Pb + (size_t)gr * 256 + c8);
    *(uint4*)(As + r * LDAB + c8) = va;
  }
  // B tile: 2048 uint4
#pragma unroll
  for (int it = 0; it < 8; it++) {
    int lin = it * 256 + tid;
    int r = lin >> 5;
    int c8 = (lin & 31) << 3;
    *(uint4*)(Bs + r * LDAB + c8) = *(const uint4*)(Bsrc + (size_t)r * 256 + c8);
  }
  if (tid < 64) sbias[tid] = bias[ncol_base + tid];
  __syncthreads();

  int warp = tid >> 5, lane = tid & 31;
  int mw = warp >> 1, nw = warp & 1;
  int mrow0 = mw * 32, ncol0 = nw * 32;
  int qr = lane >> 2, qc = lane & 3;

  float acc[2][4][4];
#pragma unroll
  for (int mi = 0; mi < 2; mi++)
#pragma unroll
    for (int ni = 0; ni < 4; ni++)
#pragma unroll
      for (int q = 0; q < 4; q++) acc[mi][ni][q] = 0.f;

#pragma unroll
  for (int kk = 0; kk < 16; kk++) {
    int kb = kk * 16 + qc * 2;
    uint32_t a[2][4], b[4][2];
#pragma unroll
    for (int mi = 0; mi < 2; mi++) {
      const __nv_bfloat16* ap = As + (mrow0 + mi * 16 + qr) * LDAB + kb;
      a[mi][0] = *(const uint32_t*)(ap);
      a[mi][1] = *(const uint32_t*)(ap + 8 * LDAB);
      a[mi][2] = *(const uint32_t*)(ap + 8);
      a[mi][3] = *(const uint32_t*)(ap + 8 * LDAB + 8);
    }
#pragma unroll
    for (int ni = 0; ni < 4; ni++) {
      const __nv_bfloat16* bp = Bs + (ncol0 + ni * 8 + qr) * LDAB + kb;
      b[ni][0] = *(const uint32_t*)(bp);
      b[ni][1] = *(const uint32_t*)(bp + 8);
    }
#pragma unroll
    for (int mi = 0; mi < 2; mi++)
#pragma unroll
      for (int ni = 0; ni < 4; ni++) mma16816(acc[mi][ni], a[mi], b[ni], acc[mi][ni]);
  }

  // epilogue: bias + ssp, write bf16
#pragma unroll
  for (int mi = 0; mi < 2; mi++) {
    int r1 = row0 + mrow0 + mi * 16 + qr;
    int r2 = r1 + 8;
#pragma unroll
    for (int ni = 0; ni < 4; ni++) {
      int lc = ncol0 + ni * 8 + qc * 2;   // local col within 64
      int cc = ncol_base + lc;            // global col
      float bz0 = sbias[lc], bz1 = sbias[lc + 1];
      if (r1 < NN) {
        __nv_bfloat162 o = __float22bfloat162_rn(
            make_float2(ssp_f(acc[mi][ni][0] + bz0), ssp_f(acc[mi][ni][1] + bz1)));
        *(uint32_t*)(g_vb + (size_t)r1 * 128 + cc) = *(uint32_t*)&o;
      }
      if (r2 < NN) {
        __nv_bfloat162 o = __float22bfloat162_rn(
            make_float2(ssp_f(acc[mi][ni][2] + bz0), ssp_f(acc[mi][ni][3] + bz1)));
        *(uint32_t*)(g_vb + (size_t)r2 * 128 + cc) = *(uint32_t*)&o;
      }
    }
  }
}

// ---------------- fused fp32 readout: out += ssp(v@W1+b1)@W2 + b2 (segment-summed) ----------------
__global__ __launch_bounds__(256) void k_ro(const float* __restrict__ W1,
                                            const float* __restrict__ b1,
                                            const float* __restrict__ W2,
                                            const float* __restrict__ b2,
                                            const int* __restrict__ batch,
                                            float* __restrict__ out) {
  __shared__ float As[16][64];
  __shared__ float Bs[16][64];
  __shared__ float sb1[64], sW2[64];
  int tid = threadIdx.x;
  int row0 = blockIdx.x * 64;
  int ty = tid >> 4, tx = tid & 15;
  float acc[4][4];
#pragma unroll
  for (int i = 0; i < 4; i++)
#pragma unroll
    for (int j = 0; j < 4; j++) acc[i][j] = 0.f;

  int a_r = tid >> 2, a_c = (tid & 3) << 2;
  int b_r = tid >> 4, b_c = (tid & 15) << 2;
  int grow = row0 + a_r;
  bool avalid = grow < NN;
  const __nv_bfloat16* Aptr = g_vb + (size_t)(avalid ? grow : 0) * 128 + a_c;
  if (tid < 64) { sb1[tid] = b1[tid]; sW2[tid] = W2[tid]; }

  for (int k0 = 0; k0 < 128; k0 += 16) {
    float2 f0 = make_float2(0.f, 0.f), f1 = make_float2(0.f, 0.f);
    if (avalid) {
      uint2 raw = *(const uint2*)(Aptr + k0);
      f0 = __bfloat1622float2(*(__nv_bfloat162*)&raw.x);
      f1 = __bfloat1622float2(*(__nv_bfloat162*)&raw.y);
    }
    float4 bv = *(const float4*)(W1 + (size_t)(k0 + b_r) * 64 + b_c);
    As[a_c + 0][a_r] = f0.x;
    As[a_c + 1][a_r] = f0.y;
    As[a_c + 2][a_r] = f1.x;
    As[a_c + 3][a_r] = f1.y;
    *(float4*)&Bs[b_r][b_c] = bv;
    __syncthreads();
#pragma unroll
    for (int kk = 0; kk < 16; kk++) {
      float a[4], b[4];
      *(float4*)(a) = *(const float4*)&As[kk][ty * 4];
      *(float4*)(b) = *(const float4*)&Bs[kk][tx * 4];
#pragma unroll
      for (int i = 0; i < 4; i++)
#pragma unroll
        for (int j = 0; j < 4; j++) acc[i][j] = fmaf(a[i], b[j], acc[i][j]);
    }
    __syncthreads();
  }

  float bz2 = b2[0];
#pragma unroll
  for (int i = 0; i < 4; i++) {
    int r = row0 + ty * 4 + i;
    float p = 0.f;
#pragma unroll
    for (int j = 0; j < 4; j++)
      p = fmaf(ssp_f(acc[i][j] + sb1[tx * 4 + j]), sW2[tx * 4 + j], p);
    p += __shfl_xor_sync(0xffffffffu, p, 1);
    p += __shfl_xor_sync(0xffffffffu, p, 2);
    p += __shfl_xor_sync(0xffffffffu, p, 4);
    p += __shfl_xor_sync(0xffffffffu, p, 8);
    if (tx == 0 && r < NN) atomicAdd(&out[batch[r]], p + bz2);
  }
}

// ---------------- launch ----------------
extern "C" void kernel_launch(void* const* d_in, const int* in_sizes, int n_in,
                              void* d_out, int out_size) {
  (void)in_sizes; (void)n_in;
  const int* z = (const int*)d_in[0];
  const float* pos = (const float*)d_in[1];
  const int* batch = (const int*)d_in[2];
  const int* ei = (const int*)d_in[3];
  const float* emb = (const float*)d_in[4];
  const float* dist_W = (const float*)d_in[5];
  const float* dist_b = (const float*)d_in[6];
  const float* Wn = (const float*)d_in[7];
  const float* We = (const float*)d_in[8];
  const float* be = (const float*)d_in[9];
  const float* Wo = (const float*)d_in[10];
  const float* bo = (const float*)d_in[11];
  const float* W1 = (const float*)d_in[12];
  const float* b1 = (const float*)d_in[13];
  const float* W2 = (const float*)d_in[14];
  const float* b2 = (const float*)d_in[15];
  float* out = (float*)d_out;

  const int* row = ei;
  const int* col = ei + EE;

  static bool attr_set = false;
  if (!attr_set) {
    cudaFuncSetAttribute(k_gemm_mma, cudaFuncAttributeMaxDynamicSharedMemorySize, SMEM_GEMM);
    attr_set = true;
  }

  const int nscan = (NN + 255) / 256;  // 196

  // CSR build (counting sort by destination row; g_cnt is zero from static init
  // on the first call and self-cleaned by k_scan3 on every subsequent replay)
  k_hist<<<(EE + 255) / 256, 256>>>(row);
  k_scan1<<<nscan, 256>>>();
  k_scan2<<<1, 256>>>(nscan);
  k_scan3<<<nscan, 256>>>();
  k_scatter<<<(EE + 255) / 256, 256>>>(row, col, pos);

  // init node features + zero output, fold per-layer weights
  k_init<<<(NN * HH + 255) / 256, 256>>>(z, emb, out, out_size);
  k_prep<<<dim3(LL, 8), 256>>>(dist_W, dist_b, Wn, We, be, Wo);

  // 6 message-passing layers (GEMM N-split: grid (391, 2), 2 CTAs/SM)
  const int ngemm = (NN + 127) / 128;  // 391
  for (int i = 0; i < LL; i++) {
    k_edge<<<(NN * 32 + 255) / 256, 256>>>();
    k_gemm_mma<<<dim3(ngemm, 2), 256, SMEM_GEMM>>>(i, bo + i * HH);
  }

  // fused fp32 readout
  k_ro<<<(NN + 63) / 64, 256>>>(W1, b1, W2, b2, batch, out);
}